// round 7
// baseline (speedup 1.0000x reference)
#include <cuda_runtime.h>
#include <math.h>
#include <stdint.h>

static constexpr int B_ = 4, S_ = 1024, DM_ = 1024, H_ = 16, DK_ = 64, DV_ = 64;
static constexpr int NX_ = B_*S_*DM_;     // 4M elements (q/k/v)
static constexpr int NW_ = H_*DM_*DK_;    // 1M elements (Wq/Wk/Wv)
static constexpr int NWO_ = DM_*H_*DV_;   // 1M elements (Wo)

// Scratch (device globals: no allocation allowed). All tf32 bit patterns.
__device__ uint32_t g_qT[NX_], g_kT[NX_], g_vT[NX_];
__device__ uint32_t g_WqT[NW_], g_WkT[NW_], g_WvT[NW_], g_WoT[NWO_];
__device__ uint32_t g_Q[B_*H_*S_*DK_];    // [b,h,s,dk], pre-scaled by 1/8
__device__ uint32_t g_K[B_*H_*S_*DK_];
__device__ uint32_t g_V[B_*H_*S_*DV_];
__device__ uint32_t g_X[B_*S_*H_*DV_];    // attn out concat heads [b,s,h*dv]

__device__ __forceinline__ uint32_t f2tf(float x) {
    uint32_t r;
    asm("cvt.rna.tf32.f32 %0, %1;" : "=r"(r) : "f"(x));
    return r;
}

// D += A * B  (m16n8k8, tf32 inputs, f32 accumulate)
__device__ __forceinline__ void mma8(float* c, const uint32_t* a, const uint32_t* b) {
    asm volatile(
        "mma.sync.aligned.m16n8k8.row.col.f32.tf32.tf32.f32 "
        "{%0,%1,%2,%3}, {%4,%5,%6,%7}, {%8,%9}, {%0,%1,%2,%3};"
        : "+f"(c[0]), "+f"(c[1]), "+f"(c[2]), "+f"(c[3])
        : "r"(a[0]), "r"(a[1]), "r"(a[2]), "r"(a[3]), "r"(b[0]), "r"(b[1]));
}

__device__ __forceinline__ void cpa16(void* smem_ptr, const void* gptr) {
    uint32_t s = (uint32_t)__cvta_generic_to_shared(smem_ptr);
    asm volatile("cp.async.cg.shared.global [%0], [%1], 16;" :: "r"(s), "l"(gptr));
}
__device__ __forceinline__ void cpa_commit() { asm volatile("cp.async.commit_group;"); }
__device__ __forceinline__ void cpa_wait0()  { asm volatile("cp.async.wait_group 0;"); }
__device__ __forceinline__ void cpa_wait1()  { asm volatile("cp.async.wait_group 1;"); }

// ---------------------------------------------------------------------------
// Kernel 0: one-time conversion of all inputs to tf32 bit patterns.
// ---------------------------------------------------------------------------
__global__ __launch_bounds__(256) void cvt_inputs(
    const float* __restrict__ q, const float* __restrict__ k, const float* __restrict__ v,
    const float* __restrict__ Wq, const float* __restrict__ Wk, const float* __restrict__ Wv,
    const float* __restrict__ Wo)
{
    const float* src; uint32_t* dst; int n;
    switch (blockIdx.y) {
        case 0: src = q;  dst = g_qT;  n = NX_;  break;
        case 1: src = k;  dst = g_kT;  n = NX_;  break;
        case 2: src = v;  dst = g_vT;  n = NX_;  break;
        case 3: src = Wq; dst = g_WqT; n = NW_;  break;
        case 4: src = Wk; dst = g_WkT; n = NW_;  break;
        case 5: src = Wv; dst = g_WvT; n = NW_;  break;
        default: src = Wo; dst = g_WoT; n = NWO_; break;
    }
    int i = (blockIdx.x * 256 + threadIdx.x) * 4;
    if (i < n) {
        float4 vl = *(const float4*)&src[i];
        *(uint4*)&dst[i] = make_uint4(f2tf(vl.x), f2tf(vl.y), f2tf(vl.z), f2tf(vl.w));
    }
}

// ---------------------------------------------------------------------------
// Kernel 1: fused QKV projections. Block 128(M) x 128(N = 2 heads), 256 thr =
// 8 warps (4m x 2n), warp tile 32x64, K-chunk 32, cp.async double-buffered.
// ---------------------------------------------------------------------------
__global__ __launch_bounds__(256, 2) void qkv_proj_mma()
{
    extern __shared__ uint32_t smq[];
    uint32_t (*As)[128][36]  = (uint32_t(*)[128][36])smq;              // 2 bufs
    uint32_t (*Bs)[32][136]  = (uint32_t(*)[32][136])(smq + 2*128*36); // 2 bufs

    const uint32_t* x; const uint32_t* W; uint32_t* out; float sc = 1.f;
    if (blockIdx.z == 0)      { x = g_qT; W = g_WqT; out = g_Q; sc = 0.125f; }
    else if (blockIdx.z == 1) { x = g_kT; W = g_WkT; out = g_K; }
    else                      { x = g_vT; W = g_WvT; out = g_V; }

    const int m0 = blockIdx.x * 128;
    const int hp = blockIdx.y;                  // head pair: heads 2hp, 2hp+1

    const int tid = threadIdx.x, lane = tid & 31, warp = tid >> 5;
    const int wm = warp & 3, wn = warp >> 2;
    const int g = lane >> 2, tig = lane & 3;

    float acc[2][8][4];
    #pragma unroll
    for (int mt = 0; mt < 2; mt++)
        #pragma unroll
        for (int nt = 0; nt < 8; nt++)
            #pragma unroll
            for (int i = 0; i < 4; i++) acc[mt][nt][i] = 0.f;

    auto issue = [&](int k0, int buf) {
        #pragma unroll
        for (int t = 0; t < 4; t++) {           // A: 128x32
            int idx = tid + t * 256, r = idx >> 3, c = (idx & 7) * 4;
            cpa16(&As[buf][r][c], &x[(size_t)(m0 + r) * DM_ + k0 + c]);
        }
        #pragma unroll
        for (int t = 0; t < 4; t++) {           // B: 32x128 (two heads)
            int idx = tid + t * 256, r = idx >> 5, c = (idx & 31) * 4;
            int h = 2 * hp + (c >> 6), cc = c & 63;
            cpa16(&Bs[buf][r][c], &W[((size_t)h * DM_ + k0 + r) * DK_ + cc]);
        }
        cpa_commit();
    };

    issue(0, 0);

    for (int it = 0; it < DM_ / 32; it++) {
        const int buf = it & 1;
        cpa_wait0();
        __syncthreads();
        if (it + 1 < DM_ / 32) issue((it + 1) * 32, buf ^ 1);

        #pragma unroll
        for (int ks = 0; ks < 4; ks++) {
            uint32_t af[2][4];
            #pragma unroll
            for (int mt = 0; mt < 2; mt++) {
                int rr = wm * 32 + mt * 16 + g;
                af[mt][0] = As[buf][rr][ks*8 + tig];
                af[mt][1] = As[buf][rr + 8][ks*8 + tig];
                af[mt][2] = As[buf][rr][ks*8 + tig + 4];
                af[mt][3] = As[buf][rr + 8][ks*8 + tig + 4];
            }
            #pragma unroll
            for (int nt = 0; nt < 8; nt++) {
                uint32_t bf[2];
                bf[0] = Bs[buf][ks*8 + tig][wn*64 + nt*8 + g];
                bf[1] = Bs[buf][ks*8 + tig + 4][wn*64 + nt*8 + g];
                mma8(acc[0][nt], af[0], bf);
                mma8(acc[1][nt], af[1], bf);
            }
        }
    }

    const int h = 2 * hp + wn;
    #pragma unroll
    for (int mt = 0; mt < 2; mt++) {
        #pragma unroll
        for (int half = 0; half < 2; half++) {
            int m = m0 + wm * 32 + mt * 16 + g + half * 8;
            int b = m >> 10, s = m & 1023;
            uint32_t* op = &out[(((size_t)b * H_ + h) * S_ + s) * DK_];
            #pragma unroll
            for (int nt = 0; nt < 8; nt++) {
                int nn = nt * 8 + 2 * tig;
                float v0 = half ? acc[mt][nt][2] : acc[mt][nt][0];
                float v1 = half ? acc[mt][nt][3] : acc[mt][nt][1];
                *(uint2*)&op[nn] = make_uint2(f2tf(v0 * sc), f2tf(v1 * sc));
            }
        }
    }
}

// ---------------------------------------------------------------------------
// Kernel 2: causal flash attention. 256 thr = 8 warps x 16 query rows
// (128-row tile). Q hoisted to registers; K/V double-buffered via cp.async.
// ---------------------------------------------------------------------------
__global__ __launch_bounds__(256, 2) void attn_mma()
{
    extern __shared__ uint32_t sm[];
    uint32_t (*Ks)[64][68] = (uint32_t(*)[64][68])sm;                  // 2 bufs
    uint32_t (*Vs)[64][72] = (uint32_t(*)[64][72])(sm + 2*64*68);      // 2 bufs
    uint32_t (*Ps)[68]     = (uint32_t(*)[68])(sm + 2*64*68 + 2*64*72); // 128x68 (also Q staging)

    const int qt = 7 - blockIdx.x;          // descending work for tail balance
    const int bh = blockIdx.y;
    const int b = bh >> 4, h = bh & 15;
    const int tid = threadIdx.x, lane = tid & 31, warp = tid >> 5;
    const int g = lane >> 2, tig = lane & 3;

    const uint32_t* Qg = g_Q + (size_t)bh * S_ * DK_ + (size_t)qt * 128 * DK_;
    const uint32_t* Kg = g_K + (size_t)bh * S_ * DK_;
    const uint32_t* Vg = g_V + (size_t)bh * S_ * DK_;

    // ---- stage Q tile into Ps region, then hoist to registers ----
    #pragma unroll
    for (int t = 0; t < 8; t++) {
        int idx = tid + t * 256, r = idx >> 4, c = (idx & 15) * 4;
        cpa16(&Ps[r][c], &Qg[r * DK_ + c]);
    }
    cpa_commit(); cpa_wait0();
    __syncthreads();

    uint32_t qf[8][4];
    {
        int rr = warp * 16 + g;
        #pragma unroll
        for (int ks = 0; ks < 8; ks++) {
            qf[ks][0] = Ps[rr][ks*8 + tig];
            qf[ks][1] = Ps[rr + 8][ks*8 + tig];
            qf[ks][2] = Ps[rr][ks*8 + tig + 4];
            qf[ks][3] = Ps[rr + 8][ks*8 + tig + 4];
        }
    }

    auto issueKV = [&](int j, int buf) {
        const uint32_t* Kt = Kg + (size_t)j * 64 * DK_;
        const uint32_t* Vt = Vg + (size_t)j * 64 * DK_;
        #pragma unroll
        for (int t = 0; t < 4; t++) {
            int idx = tid + t * 256, r = idx >> 4, c = (idx & 15) * 4;
            cpa16(&Ks[buf][r][c], &Kt[r * DK_ + c]);
            cpa16(&Vs[buf][r][c], &Vt[r * DK_ + c]);
        }
        cpa_commit();
    };

    float O[8][4];
    #pragma unroll
    for (int nt = 0; nt < 8; nt++)
        #pragma unroll
        for (int i = 0; i < 4; i++) O[nt][i] = 0.f;
    float mst[2] = {-1e30f, -1e30f};
    float lst[2] = {0.f, 0.f};

    const int base = qt * 128 + warp * 16;
    const int jmax = 2 * qt + 1;

    issueKV(0, 0);

    for (int j = 0; j <= jmax; j++) {
        const int buf = j & 1;
        __syncthreads();                 // prior compute done (buf^1 free); Q hoist done (j=0)
        if (j < jmax) { issueKV(j + 1, buf ^ 1); cpa_wait1(); }
        else          { cpa_wait0(); }
        __syncthreads();                 // tile j visible to all warps

        if (j * 64 > base + 15) continue;    // tile fully masked for this warp

        // ---- S = Q K^T  (16 rows x 64 keys per warp) ----
        float Sf[8][4];
        #pragma unroll
        for (int nt = 0; nt < 8; nt++)
            #pragma unroll
            for (int i = 0; i < 4; i++) Sf[nt][i] = 0.f;

        #pragma unroll
        for (int ks = 0; ks < 8; ks++) {
            #pragma unroll
            for (int nt = 0; nt < 8; nt++) {
                uint32_t bf[2];
                bf[0] = Ks[buf][nt*8 + g][ks*8 + tig];
                bf[1] = Ks[buf][nt*8 + g][ks*8 + tig + 4];
                mma8(Sf[nt], qf[ks], bf);
            }
        }

        // ---- causal mask (tiles touching the diagonal) ----
        if ((j + 1) * 64 > base) {
            int r0 = base + g - j * 64, r1 = r0 + 8;
            #pragma unroll
            for (int nt = 0; nt < 8; nt++) {
                int c0 = nt * 8 + 2 * tig, c1 = c0 + 1;
                if (c0 > r0) Sf[nt][0] = -1e30f;
                if (c1 > r0) Sf[nt][1] = -1e30f;
                if (c0 > r1) Sf[nt][2] = -1e30f;
                if (c1 > r1) Sf[nt][3] = -1e30f;
            }
        }

        // ---- online softmax (two row groups: g, g+8) ----
        #pragma unroll
        for (int hp = 0; hp < 2; hp++) {
            float mx = -1e30f;
            #pragma unroll
            for (int nt = 0; nt < 8; nt++)
                mx = fmaxf(mx, fmaxf(Sf[nt][2*hp], Sf[nt][2*hp+1]));
            mx = fmaxf(mx, __shfl_xor_sync(0xffffffffu, mx, 1));
            mx = fmaxf(mx, __shfl_xor_sync(0xffffffffu, mx, 2));
            const float mn = fmaxf(mst[hp], mx);
            const float fac = __expf(mst[hp] - mn);
            float ls = 0.f;
            const int rr = warp * 16 + g + 8 * hp;
            #pragma unroll
            for (int nt = 0; nt < 8; nt++) {
                float p0 = __expf(Sf[nt][2*hp]     - mn);
                float p1 = __expf(Sf[nt][2*hp + 1] - mn);
                ls += p0 + p1;
                *(uint2*)&Ps[rr][nt*8 + 2*tig] = make_uint2(f2tf(p0), f2tf(p1));
                O[nt][2*hp]     *= fac;
                O[nt][2*hp + 1] *= fac;
            }
            ls += __shfl_xor_sync(0xffffffffu, ls, 1);
            ls += __shfl_xor_sync(0xffffffffu, ls, 2);
            lst[hp] = lst[hp] * fac + ls;
            mst[hp] = mn;
        }
        __syncwarp();   // each warp consumes only its own P rows

        // ---- O += P V ----
        #pragma unroll
        for (int kt = 0; kt < 8; kt++) {
            uint32_t af[4];
            int rr = warp * 16 + g;
            af[0] = Ps[rr][kt*8 + tig];
            af[1] = Ps[rr + 8][kt*8 + tig];
            af[2] = Ps[rr][kt*8 + tig + 4];
            af[3] = Ps[rr + 8][kt*8 + tig + 4];
            #pragma unroll
            for (int nt = 0; nt < 8; nt++) {
                uint32_t bf[2];
                bf[0] = Vs[buf][kt*8 + tig][nt*8 + g];
                bf[1] = Vs[buf][kt*8 + tig + 4][nt*8 + g];
                mma8(O[nt], af, bf);
            }
        }
    }

    // epilogue: write X as tf32 bits (out_proj consumes it as mma operand)
    #pragma unroll
    for (int hp = 0; hp < 2; hp++) {
        const float rl = 1.f / lst[hp];
        const int row = base + g + 8 * hp;
        uint32_t* xp = g_X + ((size_t)b * S_ + row) * (H_ * DV_) + h * DV_;
        #pragma unroll
        for (int nt = 0; nt < 8; nt++) {
            int cc = nt * 8 + 2 * tig;
            *(uint2*)&xp[cc] = make_uint2(f2tf(O[nt][2*hp] * rl),
                                          f2tf(O[nt][2*hp + 1] * rl));
        }
    }
}

// ---------------------------------------------------------------------------
// Kernel 3: output projection  y[m,d] = sum_e X[m,e] * Wo[d,e]
// Block 128x128, 256 thr = 8 warps (4m x 2n), warp 32x64, cp.async 2-buf.
// ---------------------------------------------------------------------------
__global__ __launch_bounds__(256, 2) void out_proj_mma(float* __restrict__ y)
{
    extern __shared__ uint32_t smo[];
    uint32_t (*As)[128][36]  = (uint32_t(*)[128][36])smo;
    uint32_t (*Bsn)[128][36] = (uint32_t(*)[128][36])(smo + 2*128*36);

    const int m0 = blockIdx.x * 128;
    const int n0 = blockIdx.y * 128;

    const int tid = threadIdx.x, lane = tid & 31, warp = tid >> 5;
    const int wm = warp & 3, wn = warp >> 2;
    const int g = lane >> 2, tig = lane & 3;

    float acc[2][8][4];
    #pragma unroll
    for (int mt = 0; mt < 2; mt++)
        #pragma unroll
        for (int nt = 0; nt < 8; nt++)
            #pragma unroll
            for (int i = 0; i < 4; i++) acc[mt][nt][i] = 0.f;

    auto issue = [&](int k0, int buf) {
        #pragma unroll
        for (int t = 0; t < 4; t++) {
            int idx = tid + t * 256, r = idx >> 3, c = (idx & 7) * 4;
            cpa16(&As[buf][r][c], &g_X[(size_t)(m0 + r) * DM_ + k0 + c]);
        }
        #pragma unroll
        for (int t = 0; t < 4; t++) {
            int idx = tid + t * 256, r = idx >> 3, c = (idx & 7) * 4;
            cpa16(&Bsn[buf][r][c], &g_WoT[(size_t)(n0 + r) * DM_ + k0 + c]);
        }
        cpa_commit();
    };

    issue(0, 0);

    for (int it = 0; it < DM_ / 32; it++) {
        const int buf = it & 1;
        cpa_wait0();
        __syncthreads();
        if (it + 1 < DM_ / 32) issue((it + 1) * 32, buf ^ 1);

        #pragma unroll
        for (int ks = 0; ks < 4; ks++) {
            uint32_t af[2][4];
            #pragma unroll
            for (int mt = 0; mt < 2; mt++) {
                int rr = wm * 32 + mt * 16 + g;
                af[mt][0] = As[buf][rr][ks*8 + tig];
                af[mt][1] = As[buf][rr + 8][ks*8 + tig];
                af[mt][2] = As[buf][rr][ks*8 + tig + 4];
                af[mt][3] = As[buf][rr + 8][ks*8 + tig + 4];
            }
            #pragma unroll
            for (int nt = 0; nt < 8; nt++) {
                uint32_t bf[2];
                bf[0] = Bsn[buf][wn*64 + nt*8 + g][ks*8 + tig];
                bf[1] = Bsn[buf][wn*64 + nt*8 + g][ks*8 + tig + 4];
                mma8(acc[0][nt], af[0], bf);
                mma8(acc[1][nt], af[1], bf);
            }
        }
    }

    #pragma unroll
    for (int mt = 0; mt < 2; mt++) {
        #pragma unroll
        for (int half = 0; half < 2; half++) {
            int m = m0 + wm * 32 + mt * 16 + g + half * 8;
            #pragma unroll
            for (int nt = 0; nt < 8; nt++) {
                int nn = n0 + wn * 64 + nt * 8 + 2 * tig;
                float2 val = half ? make_float2(acc[mt][nt][2], acc[mt][nt][3])
                                  : make_float2(acc[mt][nt][0], acc[mt][nt][1]);
                *(float2*)&y[(size_t)m * DM_ + nn] = val;
            }
        }
    }
}

// ---------------------------------------------------------------------------
extern "C" void kernel_launch(void* const* d_in, const int* in_sizes, int n_in,
                              void* d_out, int out_size)
{
    const float* q  = (const float*)d_in[0];
    const float* k  = (const float*)d_in[1];
    const float* v  = (const float*)d_in[2];
    const float* Wq = (const float*)d_in[3];
    const float* Wk = (const float*)d_in[4];
    const float* Wv = (const float*)d_in[5];
    const float* Wo = (const float*)d_in[6];
    float* y = (float*)d_out;

    const int qkv_smem  = (2*128*36 + 2*32*136) * (int)sizeof(uint32_t);  // 71680
    const int oproj_smem = (2*128*36 + 2*128*36) * (int)sizeof(uint32_t); // 73728
    const int attn_smem = (2*64*68 + 2*64*72 + 128*68) * (int)sizeof(uint32_t); // 106496
    cudaFuncSetAttribute(qkv_proj_mma, cudaFuncAttributeMaxDynamicSharedMemorySize, qkv_smem);
    cudaFuncSetAttribute(attn_mma, cudaFuncAttributeMaxDynamicSharedMemorySize, attn_smem);
    cudaFuncSetAttribute(out_proj_mma, cudaFuncAttributeMaxDynamicSharedMemorySize, oproj_smem);

    cvt_inputs<<<dim3(NX_ / (256 * 4), 7), 256>>>(q, k, v, Wq, Wk, Wv, Wo);
    qkv_proj_mma<<<dim3(S_ * B_ / 128, H_ / 2, 3), 256, qkv_smem>>>();
    attn_mma<<<dim3(8, B_ * H_), 256, attn_smem>>>();
    out_proj_mma<<<dim3(S_ * B_ / 128, DM_ / 128), 256, oproj_smem>>>(y);
}

// round 10
// speedup vs baseline: 1.4199x; 1.4199x over previous
#include <cuda_runtime.h>
#include <cuda_fp16.h>
#include <math.h>
#include <stdint.h>

static constexpr int B_ = 4, S_ = 1024, DM_ = 1024, H_ = 16, DK_ = 64, DV_ = 64;
static constexpr int NX_ = B_*S_*DM_;     // 4M elements (q/k/v)
static constexpr int NWO_ = DM_*H_*DV_;   // 1M elements (Wo)

// Scratch (device globals). H = fp16x2 packed words (pairs along K dim).
__device__ uint32_t g_qH[NX_/2], g_kH[NX_/2], g_vH[NX_/2];     // [m][512w]
__device__ uint32_t g_WqH[H_*DK_*DM_/2], g_WkH[H_*DK_*DM_/2], g_WvH[H_*DK_*DM_/2]; // [h][dk][512w]
__device__ uint32_t g_WoH[NWO_/2];                             // [d][512w]
__device__ uint32_t g_QH[B_*H_*S_*DK_/2];  // [b,h,s,32w] fp16, pre-scaled by 1/8
__device__ uint32_t g_KH[B_*H_*S_*DK_/2];  // [b,h,s,32w] fp16
__device__ uint32_t g_V [B_*H_*S_*DV_];    // [b,h,s,64w] tf32 (P·V path)
__device__ uint32_t g_XH[B_*S_*H_*DV_/2];  // [b,s,512w] fp16 packed

__device__ __forceinline__ uint32_t f2tf(float x) {
    uint32_t r;
    asm("cvt.rna.tf32.f32 %0, %1;" : "=r"(r) : "f"(x));
    return r;
}
__device__ __forceinline__ uint32_t f2h2(float a, float b) {
    __half2 h = __floats2half2_rn(a, b);
    return *(uint32_t*)&h;
}

// tf32 m16n8k8 (P·V path)
__device__ __forceinline__ void mma8(float* c, const uint32_t* a, const uint32_t* b) {
    asm volatile(
        "mma.sync.aligned.m16n8k8.row.col.f32.tf32.tf32.f32 "
        "{%0,%1,%2,%3}, {%4,%5,%6,%7}, {%8,%9}, {%0,%1,%2,%3};"
        : "+f"(c[0]), "+f"(c[1]), "+f"(c[2]), "+f"(c[3])
        : "r"(a[0]), "r"(a[1]), "r"(a[2]), "r"(a[3]), "r"(b[0]), "r"(b[1]));
}
// fp16 m16n8k16, fp32 accumulate
__device__ __forceinline__ void mma16(float* c, const uint32_t* a, const uint32_t* b) {
    asm volatile(
        "mma.sync.aligned.m16n8k16.row.col.f32.f16.f16.f32 "
        "{%0,%1,%2,%3}, {%4,%5,%6,%7}, {%8,%9}, {%0,%1,%2,%3};"
        : "+f"(c[0]), "+f"(c[1]), "+f"(c[2]), "+f"(c[3])
        : "r"(a[0]), "r"(a[1]), "r"(a[2]), "r"(a[3]), "r"(b[0]), "r"(b[1]));
}

__device__ __forceinline__ void cpa16(void* smem_ptr, const void* gptr) {
    uint32_t s = (uint32_t)__cvta_generic_to_shared(smem_ptr);
    asm volatile("cp.async.cg.shared.global [%0], [%1], 16;" :: "r"(s), "l"(gptr));
}
__device__ __forceinline__ void cpa_commit() { asm volatile("cp.async.commit_group;"); }
__device__ __forceinline__ void cpa_wait0()  { asm volatile("cp.async.wait_group 0;"); }
__device__ __forceinline__ void cpa_wait1()  { asm volatile("cp.async.wait_group 1;"); }

// ---------------------------------------------------------------------------
// Kernel 0a: elementwise convert+pack q/k/v/Wo -> fp16x2 words.
// ---------------------------------------------------------------------------
__global__ __launch_bounds__(256) void cvt_pack(
    const float* __restrict__ q, const float* __restrict__ k, const float* __restrict__ v,
    const float* __restrict__ Wo)
{
    const float* src; uint32_t* dst; int n;
    switch (blockIdx.y) {
        case 0: src = q;  dst = g_qH;  n = NX_;  break;
        case 1: src = k;  dst = g_kH;  n = NX_;  break;
        case 2: src = v;  dst = g_vH;  n = NX_;  break;
        default: src = Wo; dst = g_WoH; n = NWO_; break;
    }
    int i = (blockIdx.x * 256 + threadIdx.x) * 8;
    if (i < n) {
        float4 a = *(const float4*)&src[i];
        float4 b = *(const float4*)&src[i + 4];
        uint4 o = make_uint4(f2h2(a.x, a.y), f2h2(a.z, a.w),
                             f2h2(b.x, b.y), f2h2(b.z, b.w));
        *(uint4*)&dst[i / 2] = o;
    }
}

// ---------------------------------------------------------------------------
// Kernel 0b: transpose+pack Wq/Wk/Wv: [h][dm][dk] -> [h][dk][dm/2 words].
// ---------------------------------------------------------------------------
__global__ __launch_bounds__(256) void cvt_wT(
    const float* __restrict__ Wq, const float* __restrict__ Wk, const float* __restrict__ Wv)
{
    const float* src; uint32_t* dst;
    if (blockIdx.z == 0)      { src = Wq; dst = g_WqH; }
    else if (blockIdx.z == 1) { src = Wk; dst = g_WkH; }
    else                      { src = Wv; dst = g_WvH; }

    const int h = blockIdx.y, d0 = blockIdx.x * 32;
    __shared__ float t[2][32][33];   // [dk-half][dm-local][dk-local]
    const float* Wh = src + (size_t)h * DM_ * DK_;
    for (int u = threadIdx.x; u < 2048; u += 256) {
        int i = u >> 6, nk = u & 63;
        t[nk >> 5][i][nk & 31] = Wh[(size_t)(d0 + i) * DK_ + nk];
    }
    __syncthreads();
    uint32_t* Dh = dst + (size_t)h * DK_ * (DM_ / 2);
    for (int u = threadIdx.x; u < 1024; u += 256) {
        int nk = u >> 4, i = u & 15;     // i = dm word-pair within tile
        Dh[(size_t)nk * (DM_ / 2) + d0 / 2 + i] =
            f2h2(t[nk >> 5][2 * i][nk & 31], t[nk >> 5][2 * i + 1][nk & 31]);
    }
}

// ---------------------------------------------------------------------------
// Kernel 1: fused QKV projections (fp16 mma16). Block 128(M) x 128(N=2 heads),
// 256 thr = 8 warps (4m x 2n), warp 32x64. K-chunk 32 elems = 16 words.
// Out: Q/K fp16-packed (Q scaled 1/8), V tf32.
// ---------------------------------------------------------------------------
__global__ __launch_bounds__(256, 2) void qkv_proj_mma()
{
    extern __shared__ uint32_t smq[];
    uint32_t (*As)[128][20] = (uint32_t(*)[128][20])smq;               // 2 bufs
    uint32_t (*Bs)[128][20] = (uint32_t(*)[128][20])(smq + 2*128*20);  // 2 bufs [n][kw]

    const uint32_t* x; const uint32_t* W; const int zsel = blockIdx.z;
    if (zsel == 0)      { x = g_qH; W = g_WqH; }
    else if (zsel == 1) { x = g_kH; W = g_WkH; }
    else                { x = g_vH; W = g_WvH; }

    const int m0 = blockIdx.x * 128;
    const int hp = blockIdx.y;                  // heads 2hp, 2hp+1

    const int tid = threadIdx.x, lane = tid & 31, warp = tid >> 5;
    const int wm = warp & 3, wn = warp >> 2;
    const int g = lane >> 2, tig = lane & 3;

    float acc[2][8][4];
    #pragma unroll
    for (int mt = 0; mt < 2; mt++)
        #pragma unroll
        for (int nt = 0; nt < 8; nt++)
            #pragma unroll
            for (int i = 0; i < 4; i++) acc[mt][nt][i] = 0.f;

    auto issue = [&](int k0w, int buf) {
        #pragma unroll
        for (int t = 0; t < 2; t++) {           // A: 128 rows x 16 words
            int idx = tid + t * 256, r = idx >> 2, c = (idx & 3) * 4;
            cpa16(&As[buf][r][c], &x[(size_t)(m0 + r) * (DM_/2) + k0w + c]);
        }
        #pragma unroll
        for (int t = 0; t < 2; t++) {           // B: 128 n-rows x 16 words
            int idx = tid + t * 256, r = idx >> 2, c = (idx & 3) * 4;
            int h = 2 * hp + (r >> 6), nk = r & 63;
            cpa16(&Bs[buf][r][c], &W[((size_t)h * DK_ + nk) * (DM_/2) + k0w + c]);
        }
        cpa_commit();
    };

    issue(0, 0);

    const int NCH = DM_ / 32;   // 32 chunks of 16 words
    for (int it = 0; it < NCH; it++) {
        const int buf = it & 1;
        cpa_wait0();
        __syncthreads();
        if (it + 1 < NCH) issue((it + 1) * 16, buf ^ 1);

        #pragma unroll
        for (int ks = 0; ks < 2; ks++) {
            uint32_t af[2][4];
            #pragma unroll
            for (int mt = 0; mt < 2; mt++) {
                int rr = wm * 32 + mt * 16 + g;
                af[mt][0] = As[buf][rr][ks*8 + tig];
                af[mt][1] = As[buf][rr + 8][ks*8 + tig];
                af[mt][2] = As[buf][rr][ks*8 + tig + 4];
                af[mt][3] = As[buf][rr + 8][ks*8 + tig + 4];
            }
            #pragma unroll
            for (int nt = 0; nt < 8; nt++) {
                uint32_t bf[2];
                int n = wn * 64 + nt * 8 + g;
                bf[0] = Bs[buf][n][ks*8 + tig];
                bf[1] = Bs[buf][n][ks*8 + tig + 4];
                mma16(acc[0][nt], af[0], bf);
                mma16(acc[1][nt], af[1], bf);
            }
        }
    }

    const int h = 2 * hp + wn;
    const float sc = (zsel == 0) ? 0.125f : 1.f;
    #pragma unroll
    for (int mt = 0; mt < 2; mt++) {
        #pragma unroll
        for (int half = 0; half < 2; half++) {
            int m = m0 + wm * 32 + mt * 16 + g + half * 8;
            int b = m >> 10, s = m & 1023;
            if (zsel == 2) {
                uint32_t* op = &g_V[(((size_t)b * H_ + h) * S_ + s) * DV_];
                #pragma unroll
                for (int nt = 0; nt < 8; nt++) {
                    int nn = nt * 8 + 2 * tig;
                    float v0 = half ? acc[mt][nt][2] : acc[mt][nt][0];
                    float v1 = half ? acc[mt][nt][3] : acc[mt][nt][1];
                    *(uint2*)&op[nn] = make_uint2(f2tf(v0), f2tf(v1));
                }
            } else {
                uint32_t* op = (zsel == 0 ? g_QH : g_KH)
                             + (((size_t)b * H_ + h) * S_ + s) * (DK_/2);
                #pragma unroll
                for (int nt = 0; nt < 8; nt++) {
                    float v0 = half ? acc[mt][nt][2] : acc[mt][nt][0];
                    float v1 = half ? acc[mt][nt][3] : acc[mt][nt][1];
                    op[nt * 4 + tig] = f2h2(v0 * sc, v1 * sc);
                }
            }
        }
    }
}

// ---------------------------------------------------------------------------
// Kernel 2: causal flash attention. 256 thr = 8 warps x 16 query rows.
// QK^T in fp16 (mma16), P·V in tf32 (mma8). K/V double-buffered cp.async.
// ---------------------------------------------------------------------------
__global__ __launch_bounds__(256, 2) void attn_mma()
{
    extern __shared__ uint32_t sm[];
    uint32_t (*Ks)[64][36] = (uint32_t(*)[64][36])sm;                   // 2 bufs fp16 [key][kw]
    uint32_t (*Vs)[64][72] = (uint32_t(*)[64][72])(sm + 2*64*36);       // 2 bufs tf32 [key][dv]
    uint32_t (*Ps)[68]     = (uint32_t(*)[68])(sm + 2*64*36 + 2*64*72); // 128x68 tf32
    uint32_t (*Qst)[36]    = (uint32_t(*)[36])Ps;                       // Q staging alias

    const int qt = 7 - blockIdx.x;
    const int bh = blockIdx.y;
    const int b = bh >> 4, h = bh & 15;
    const int tid = threadIdx.x, lane = tid & 31, warp = tid >> 5;
    const int g = lane >> 2, tig = lane & 3;

    const uint32_t* Qg = g_QH + (size_t)bh * S_ * (DK_/2) + (size_t)qt * 128 * (DK_/2);
    const uint32_t* Kg = g_KH + (size_t)bh * S_ * (DK_/2);
    const uint32_t* Vg = g_V  + (size_t)bh * S_ * DV_;

    // stage Q tile (fp16 packed, pre-scaled) into Ps region, stride 36
    #pragma unroll
    for (int t = 0; t < 4; t++) {
        int idx = tid + t * 256, r = idx >> 3, c = (idx & 7) * 4;
        cpa16(&Qst[r][c], &Qg[r * (DK_/2) + c]);
    }
    cpa_commit(); cpa_wait0();
    __syncthreads();

    uint32_t qf[4][4];
    {
        int rr = warp * 16 + g;
        #pragma unroll
        for (int ks = 0; ks < 4; ks++) {
            qf[ks][0] = Qst[rr][ks*8 + tig];
            qf[ks][1] = Qst[rr + 8][ks*8 + tig];
            qf[ks][2] = Qst[rr][ks*8 + tig + 4];
            qf[ks][3] = Qst[rr + 8][ks*8 + tig + 4];
        }
    }

    auto issueKV = [&](int j, int buf) {
        const uint32_t* Kt = Kg + (size_t)j * 64 * (DK_/2);
        const uint32_t* Vt = Vg + (size_t)j * 64 * DV_;
        #pragma unroll
        for (int t = 0; t < 2; t++) {            // K: 64 x 32 words
            int idx = tid + t * 256, r = idx >> 3, c = (idx & 7) * 4;
            cpa16(&Ks[buf][r][c], &Kt[r * (DK_/2) + c]);
        }
        #pragma unroll
        for (int t = 0; t < 4; t++) {            // V: 64 x 64 words
            int idx = tid + t * 256, r = idx >> 4, c = (idx & 15) * 4;
            cpa16(&Vs[buf][r][c], &Vt[r * DV_ + c]);
        }
        cpa_commit();
    };

    float O[8][4];
    #pragma unroll
    for (int nt = 0; nt < 8; nt++)
        #pragma unroll
        for (int i = 0; i < 4; i++) O[nt][i] = 0.f;
    float mst[2] = {-1e30f, -1e30f};
    float lst[2] = {0.f, 0.f};

    const int base = qt * 128 + warp * 16;
    const int jmax = 2 * qt + 1;

    issueKV(0, 0);

    for (int j = 0; j <= jmax; j++) {
        const int buf = j & 1;
        __syncthreads();                 // prior compute done; Q hoist done (j=0)
        if (j < jmax) { issueKV(j + 1, buf ^ 1); cpa_wait1(); }
        else          { cpa_wait0(); }
        __syncthreads();

        if (j * 64 > base + 15) continue;

        // ---- S = Q K^T (fp16, 16 rows x 64 keys per warp) ----
        float Sf[8][4];
        #pragma unroll
        for (int nt = 0; nt < 8; nt++)
            #pragma unroll
            for (int i = 0; i < 4; i++) Sf[nt][i] = 0.f;

        #pragma unroll
        for (int ks = 0; ks < 4; ks++) {
            #pragma unroll
            for (int nt = 0; nt < 8; nt++) {
                uint32_t bf[2];
                bf[0] = Ks[buf][nt*8 + g][ks*8 + tig];
                bf[1] = Ks[buf][nt*8 + g][ks*8 + tig + 4];
                mma16(Sf[nt], qf[ks], bf);
            }
        }

        if ((j + 1) * 64 > base) {
            int r0 = base + g - j * 64, r1 = r0 + 8;
            #pragma unroll
            for (int nt = 0; nt < 8; nt++) {
                int c0 = nt * 8 + 2 * tig, c1 = c0 + 1;
                if (c0 > r0) Sf[nt][0] = -1e30f;
                if (c1 > r0) Sf[nt][1] = -1e30f;
                if (c0 > r1) Sf[nt][2] = -1e30f;
                if (c1 > r1) Sf[nt][3] = -1e30f;
            }
        }

        #pragma unroll
        for (int hp = 0; hp < 2; hp++) {
            float mx = -1e30f;
            #pragma unroll
            for (int nt = 0; nt < 8; nt++)
                mx = fmaxf(mx, fmaxf(Sf[nt][2*hp], Sf[nt][2*hp+1]));
            mx = fmaxf(mx, __shfl_xor_sync(0xffffffffu, mx, 1));
            mx = fmaxf(mx, __shfl_xor_sync(0xffffffffu, mx, 2));
            const float mn = fmaxf(mst[hp], mx);
            const float fac = __expf(mst[hp] - mn);
            float ls = 0.f;
            const int rr = warp * 16 + g + 8 * hp;
            #pragma unroll
            for (int nt = 0; nt < 8; nt++) {
                float p0 = __expf(Sf[nt][2*hp]     - mn);
                float p1 = __expf(Sf[nt][2*hp + 1] - mn);
                ls += p0 + p1;
                *(uint2*)&Ps[rr][nt*8 + 2*tig] = make_uint2(f2tf(p0), f2tf(p1));
                O[nt][2*hp]     *= fac;
                O[nt][2*hp + 1] *= fac;
            }
            ls += __shfl_xor_sync(0xffffffffu, ls, 1);
            ls += __shfl_xor_sync(0xffffffffu, ls, 2);
            lst[hp] = lst[hp] * fac + ls;
            mst[hp] = mn;
        }
        __syncwarp();   // each warp consumes only its own P rows

        // ---- O += P V (tf32) ----
        #pragma unroll
        for (int kt = 0; kt < 8; kt++) {
            uint32_t af[4];
            int rr = warp * 16 + g;
            af[0] = Ps[rr][kt*8 + tig];
            af[1] = Ps[rr + 8][kt*8 + tig];
            af[2] = Ps[rr][kt*8 + tig + 4];
            af[3] = Ps[rr + 8][kt*8 + tig + 4];
            #pragma unroll
            for (int nt = 0; nt < 8; nt++) {
                uint32_t bf[2];
                bf[0] = Vs[buf][kt*8 + tig][nt*8 + g];
                bf[1] = Vs[buf][kt*8 + tig + 4][nt*8 + g];
                mma8(O[nt], af, bf);
            }
        }
    }

    // epilogue: pack X as fp16x2 (out_proj operand)
    #pragma unroll
    for (int hp = 0; hp < 2; hp++) {
        const float rl = 1.f / lst[hp];
        const int row = base + g + 8 * hp;
        uint32_t* xp = g_XH + ((size_t)b * S_ + row) * (H_ * DV_ / 2) + h * (DV_/2);
        #pragma unroll
        for (int nt = 0; nt < 8; nt++)
            xp[nt * 4 + tig] = f2h2(O[nt][2*hp] * rl, O[nt][2*hp + 1] * rl);
    }
}

// ---------------------------------------------------------------------------
// Kernel 3: output projection (fp16 mma16). y[m,d] = sum_e X[m,e] * Wo[d,e].
// Block 128x128, 8 warps (4m x 2n), warp 32x64.
// ---------------------------------------------------------------------------
__global__ __launch_bounds__(256, 2) void out_proj_mma(float* __restrict__ y)
{
    extern __shared__ uint32_t smo[];
    uint32_t (*As)[128][20]  = (uint32_t(*)[128][20])smo;
    uint32_t (*Bsn)[128][20] = (uint32_t(*)[128][20])(smo + 2*128*20);

    const int m0 = blockIdx.x * 128;
    const int n0 = blockIdx.y * 128;

    const int tid = threadIdx.x, lane = tid & 31, warp = tid >> 5;
    const int wm = warp & 3, wn = warp >> 2;
    const int g = lane >> 2, tig = lane & 3;

    float acc[2][8][4];
    #pragma unroll
    for (int mt = 0; mt < 2; mt++)
        #pragma unroll
        for (int nt = 0; nt < 8; nt++)
            #pragma unroll
            for (int i = 0; i < 4; i++) acc[mt][nt][i] = 0.f;

    auto issue = [&](int k0w, int buf) {
        #pragma unroll
        for (int t = 0; t < 2; t++) {
            int idx = tid + t * 256, r = idx >> 2, c = (idx & 3) * 4;
            cpa16(&As[buf][r][c], &g_XH[(size_t)(m0 + r) * (DM_/2) + k0w + c]);
        }
        #pragma unroll
        for (int t = 0; t < 2; t++) {
            int idx = tid + t * 256, r = idx >> 2, c = (idx & 3) * 4;
            cpa16(&Bsn[buf][r][c], &g_WoH[(size_t)(n0 + r) * (DM_/2) + k0w + c]);
        }
        cpa_commit();
    };

    issue(0, 0);

    const int NCH = DM_ / 32;
    for (int it = 0; it < NCH; it++) {
        const int buf = it & 1;
        cpa_wait0();
        __syncthreads();
        if (it + 1 < NCH) issue((it + 1) * 16, buf ^ 1);

        #pragma unroll
        for (int ks = 0; ks < 2; ks++) {
            uint32_t af[2][4];
            #pragma unroll
            for (int mt = 0; mt < 2; mt++) {
                int rr = wm * 32 + mt * 16 + g;
                af[mt][0] = As[buf][rr][ks*8 + tig];
                af[mt][1] = As[buf][rr + 8][ks*8 + tig];
                af[mt][2] = As[buf][rr][ks*8 + tig + 4];
                af[mt][3] = As[buf][rr + 8][ks*8 + tig + 4];
            }
            #pragma unroll
            for (int nt = 0; nt < 8; nt++) {
                uint32_t bf[2];
                int n = wn * 64 + nt * 8 + g;
                bf[0] = Bsn[buf][n][ks*8 + tig];
                bf[1] = Bsn[buf][n][ks*8 + tig + 4];
                mma16(acc[0][nt], af[0], bf);
                mma16(acc[1][nt], af[1], bf);
            }
        }
    }

    #pragma unroll
    for (int mt = 0; mt < 2; mt++) {
        #pragma unroll
        for (int half = 0; half < 2; half++) {
            int m = m0 + wm * 32 + mt * 16 + g + half * 8;
            #pragma unroll
            for (int nt = 0; nt < 8; nt++) {
                int nn = n0 + wn * 64 + nt * 8 + 2 * tig;
                float2 val = half ? make_float2(acc[mt][nt][2], acc[mt][nt][3])
                                  : make_float2(acc[mt][nt][0], acc[mt][nt][1]);
                *(float2*)&y[(size_t)m * DM_ + nn] = val;
            }
        }
    }
}

// ---------------------------------------------------------------------------
extern "C" void kernel_launch(void* const* d_in, const int* in_sizes, int n_in,
                              void* d_out, int out_size)
{
    const float* q  = (const float*)d_in[0];
    const float* k  = (const float*)d_in[1];
    const float* v  = (const float*)d_in[2];
    const float* Wq = (const float*)d_in[3];
    const float* Wk = (const float*)d_in[4];
    const float* Wv = (const float*)d_in[5];
    const float* Wo = (const float*)d_in[6];
    float* y = (float*)d_out;

    const int gemm_smem = (2*128*20 + 2*128*20) * (int)sizeof(uint32_t);  // 40960
    const int attn_smem = (2*64*36 + 2*64*72 + 128*68) * (int)sizeof(uint32_t); // 90112
    cudaFuncSetAttribute(qkv_proj_mma, cudaFuncAttributeMaxDynamicSharedMemorySize, gemm_smem);
    cudaFuncSetAttribute(attn_mma, cudaFuncAttributeMaxDynamicSharedMemorySize, attn_smem);
    cudaFuncSetAttribute(out_proj_mma, cudaFuncAttributeMaxDynamicSharedMemorySize, gemm_smem);

    cvt_pack<<<dim3(NX_ / 2048, 4), 256>>>(q, k, v, Wo);
    cvt_wT<<<dim3(DM_ / 32, H_, 3), 256>>>(Wq, Wk, Wv);
    qkv_proj_mma<<<dim3(S_ * B_ / 128, H_ / 2, 3), 256, gemm_smem>>>();
    attn_mma<<<dim3(8, B_ * H_), 256, attn_smem>>>();
    out_proj_mma<<<dim3(S_ * B_ / 128, DM_ / 128), 256, gemm_smem>>>(y);
}

// round 11
// speedup vs baseline: 1.7126x; 1.2061x over previous
#include <cuda_runtime.h>
#include <cuda_fp16.h>
#include <math.h>
#include <stdint.h>

static constexpr int B_ = 4, S_ = 1024, DM_ = 1024, H_ = 16, DK_ = 64, DV_ = 64;
static constexpr int NX_ = B_*S_*DM_;     // 4M elements (q/k/v)
static constexpr int NWO_ = DM_*H_*DV_;   // 1M elements (Wo)

// Scratch (device globals). All fp16x2 packed words (pairs along K of each GEMM).
__device__ uint32_t g_qH[NX_/2], g_kH[NX_/2], g_vH[NX_/2];     // [m][512w]
__device__ uint32_t g_WqH[H_*DK_*DM_/2], g_WkH[H_*DK_*DM_/2], g_WvH[H_*DK_*DM_/2]; // [h][dk][512w]
__device__ uint32_t g_WoH[NWO_/2];                             // [d][512w]
__device__ uint32_t g_QH[B_*H_*S_*DK_/2];  // [b,h,s,32w] fp16, pre-scaled by 1/8
__device__ uint32_t g_KH[B_*H_*S_*DK_/2];  // [b,h,s,32w] fp16
__device__ uint32_t g_VH[B_*H_*DV_*S_/2];  // V^T: [b,h,dv][512w], pairs along seq
__device__ uint32_t g_XH[B_*S_*H_*DV_/2];  // [b,s,512w] fp16 packed

__device__ __forceinline__ uint32_t f2h2(float a, float b) {
    __half2 h = __floats2half2_rn(a, b);
    return *(uint32_t*)&h;
}

// fp16 m16n8k16, fp32 accumulate
__device__ __forceinline__ void mma16(float* c, const uint32_t* a, const uint32_t* b) {
    asm volatile(
        "mma.sync.aligned.m16n8k16.row.col.f32.f16.f16.f32 "
        "{%0,%1,%2,%3}, {%4,%5,%6,%7}, {%8,%9}, {%0,%1,%2,%3};"
        : "+f"(c[0]), "+f"(c[1]), "+f"(c[2]), "+f"(c[3])
        : "r"(a[0]), "r"(a[1]), "r"(a[2]), "r"(a[3]), "r"(b[0]), "r"(b[1]));
}

__device__ __forceinline__ void cpa16(void* smem_ptr, const void* gptr) {
    uint32_t s = (uint32_t)__cvta_generic_to_shared(smem_ptr);
    asm volatile("cp.async.cg.shared.global [%0], [%1], 16;" :: "r"(s), "l"(gptr));
}
__device__ __forceinline__ void cpa_commit() { asm volatile("cp.async.commit_group;"); }
__device__ __forceinline__ void cpa_wait0()  { asm volatile("cp.async.wait_group 0;"); }
__device__ __forceinline__ void cpa_wait1()  { asm volatile("cp.async.wait_group 1;"); }

// ---------------------------------------------------------------------------
// Kernel 0a: elementwise convert+pack q/k/v/Wo -> fp16x2 words.
// ---------------------------------------------------------------------------
__global__ __launch_bounds__(256) void cvt_pack(
    const float* __restrict__ q, const float* __restrict__ k, const float* __restrict__ v,
    const float* __restrict__ Wo)
{
    const float* src; uint32_t* dst; int n;
    switch (blockIdx.y) {
        case 0: src = q;  dst = g_qH;  n = NX_;  break;
        case 1: src = k;  dst = g_kH;  n = NX_;  break;
        case 2: src = v;  dst = g_vH;  n = NX_;  break;
        default: src = Wo; dst = g_WoH; n = NWO_; break;
    }
    int i = (blockIdx.x * 256 + threadIdx.x) * 8;
    if (i < n) {
        float4 a = *(const float4*)&src[i];
        float4 b = *(const float4*)&src[i + 4];
        uint4 o = make_uint4(f2h2(a.x, a.y), f2h2(a.z, a.w),
                             f2h2(b.x, b.y), f2h2(b.z, b.w));
        *(uint4*)&dst[i / 2] = o;
    }
}

// ---------------------------------------------------------------------------
// Kernel 0b: transpose+pack Wq/Wk/Wv: [h][dm][dk] -> [h][dk][dm/2 words].
// ---------------------------------------------------------------------------
__global__ __launch_bounds__(256) void cvt_wT(
    const float* __restrict__ Wq, const float* __restrict__ Wk, const float* __restrict__ Wv)
{
    const float* src; uint32_t* dst;
    if (blockIdx.z == 0)      { src = Wq; dst = g_WqH; }
    else if (blockIdx.z == 1) { src = Wk; dst = g_WkH; }
    else                      { src = Wv; dst = g_WvH; }

    const int h = blockIdx.y, d0 = blockIdx.x * 32;
    __shared__ float t[2][32][33];   // [dk-half][dm-local][dk-local]
    const float* Wh = src + (size_t)h * DM_ * DK_;
    for (int u = threadIdx.x; u < 2048; u += 256) {
        int i = u >> 6, nk = u & 63;
        t[nk >> 5][i][nk & 31] = Wh[(size_t)(d0 + i) * DK_ + nk];
    }
    __syncthreads();
    uint32_t* Dh = dst + (size_t)h * DK_ * (DM_ / 2);
    for (int u = threadIdx.x; u < 1024; u += 256) {
        int nk = u >> 4, i = u & 15;     // i = dm word-pair within tile
        Dh[(size_t)nk * (DM_ / 2) + d0 / 2 + i] =
            f2h2(t[nk >> 5][2 * i][nk & 31], t[nk >> 5][2 * i + 1][nk & 31]);
    }
}

// ---------------------------------------------------------------------------
// Kernel 1: fused QKV projections (fp16 mma16). Block 128(M) x 128(N=2 heads),
// 256 thr = 8 warps (4m x 2n), warp 32x64. K-chunk 64 elems = 32 words.
// Out: Q/K fp16 [s][dk-words] (Q scaled 1/8); V fp16 TRANSPOSED [dv][s-words].
// ---------------------------------------------------------------------------
__global__ __launch_bounds__(256, 2) void qkv_proj_mma()
{
    extern __shared__ uint32_t smq[];
    uint32_t (*As)[128][36] = (uint32_t(*)[128][36])smq;               // 2 bufs
    uint32_t (*Bs)[128][36] = (uint32_t(*)[128][36])(smq + 2*128*36);  // 2 bufs [n][kw]

    const uint32_t* x; const uint32_t* W; const int zsel = blockIdx.z;
    if (zsel == 0)      { x = g_qH; W = g_WqH; }
    else if (zsel == 1) { x = g_kH; W = g_WkH; }
    else                { x = g_vH; W = g_WvH; }

    const int m0 = blockIdx.x * 128;
    const int hp = blockIdx.y;                  // heads 2hp, 2hp+1

    const int tid = threadIdx.x, lane = tid & 31, warp = tid >> 5;
    const int wm = warp & 3, wn = warp >> 2;
    const int g = lane >> 2, tig = lane & 3;

    float acc[2][8][4];
    #pragma unroll
    for (int mt = 0; mt < 2; mt++)
        #pragma unroll
        for (int nt = 0; nt < 8; nt++)
            #pragma unroll
            for (int i = 0; i < 4; i++) acc[mt][nt][i] = 0.f;

    auto issue = [&](int k0w, int buf) {
        #pragma unroll
        for (int t = 0; t < 4; t++) {           // A: 128 rows x 32 words
            int idx = tid + t * 256, r = idx >> 3, c = (idx & 7) * 4;
            cpa16(&As[buf][r][c], &x[(size_t)(m0 + r) * (DM_/2) + k0w + c]);
        }
        #pragma unroll
        for (int t = 0; t < 4; t++) {           // B: 128 n-rows x 32 words
            int idx = tid + t * 256, r = idx >> 3, c = (idx & 7) * 4;
            int h = 2 * hp + (r >> 6), nk = r & 63;
            cpa16(&Bs[buf][r][c], &W[((size_t)h * DK_ + nk) * (DM_/2) + k0w + c]);
        }
        cpa_commit();
    };

    issue(0, 0);

    const int NCH = DM_ / 64;   // 16 chunks of 32 words
    for (int it = 0; it < NCH; it++) {
        const int buf = it & 1;
        cpa_wait0();
        __syncthreads();
        if (it + 1 < NCH) issue((it + 1) * 32, buf ^ 1);

        #pragma unroll
        for (int ks = 0; ks < 4; ks++) {
            uint32_t af[2][4];
            #pragma unroll
            for (int mt = 0; mt < 2; mt++) {
                int rr = wm * 32 + mt * 16 + g;
                af[mt][0] = As[buf][rr][ks*8 + tig];
                af[mt][1] = As[buf][rr + 8][ks*8 + tig];
                af[mt][2] = As[buf][rr][ks*8 + tig + 4];
                af[mt][3] = As[buf][rr + 8][ks*8 + tig + 4];
            }
            #pragma unroll
            for (int nt = 0; nt < 8; nt++) {
                uint32_t bf[2];
                int n = wn * 64 + nt * 8 + g;
                bf[0] = Bs[buf][n][ks*8 + tig];
                bf[1] = Bs[buf][n][ks*8 + tig + 4];
                mma16(acc[0][nt], af[0], bf);
                mma16(acc[1][nt], af[1], bf);
            }
        }
    }

    if (zsel == 2) {
        // ---- V: transpose in smem, emit V^T [b,h,dv][s/2 words] fp16 ----
        __syncthreads();                       // done reading As/Bs
        __half (*smemN)[136] = (__half(*)[136])smq;   // [m(s-local)][n] halves
        #pragma unroll
        for (int mt = 0; mt < 2; mt++)
            #pragma unroll
            for (int hf = 0; hf < 2; hf++) {
                int lm = wm * 32 + mt * 16 + g + hf * 8;
                #pragma unroll
                for (int nt = 0; nt < 8; nt++) {
                    int c0 = wn * 64 + nt * 8 + 2 * tig;
                    float v0 = hf ? acc[mt][nt][2] : acc[mt][nt][0];
                    float v1 = hf ? acc[mt][nt][3] : acc[mt][nt][1];
                    *(__half2*)&smemN[lm][c0] = __floats2half2_rn(v0, v1);
                }
            }
        __syncthreads();
        const int b = m0 >> 10, s0 = m0 & 1023;
        #pragma unroll
        for (int t = 0; t < 32; t++) {
            int u = tid + t * 256;              // 8192 output words
            int r = u >> 6, w = u & 63;         // r = n index, w = s word
            int h = 2 * hp + (r >> 6), dv = r & 63;
            __half2 hh;
            hh.x = smemN[2 * w][r];
            hh.y = smemN[2 * w + 1][r];
            g_VH[(((size_t)b * H_ + h) * DV_ + dv) * (S_/2) + s0 / 2 + w] = *(uint32_t*)&hh;
        }
    } else {
        const int h = 2 * hp + wn;
        const float sc = (zsel == 0) ? 0.125f : 1.f;
        uint32_t* outb = (zsel == 0) ? g_QH : g_KH;
        #pragma unroll
        for (int mt = 0; mt < 2; mt++) {
            #pragma unroll
            for (int hf = 0; hf < 2; hf++) {
                int m = m0 + wm * 32 + mt * 16 + g + hf * 8;
                int b = m >> 10, s = m & 1023;
                uint32_t* op = outb + (((size_t)b * H_ + h) * S_ + s) * (DK_/2);
                #pragma unroll
                for (int nt = 0; nt < 8; nt++) {
                    float v0 = hf ? acc[mt][nt][2] : acc[mt][nt][0];
                    float v1 = hf ? acc[mt][nt][3] : acc[mt][nt][1];
                    op[nt * 4 + tig] = f2h2(v0 * sc, v1 * sc);
                }
            }
        }
    }
}

// ---------------------------------------------------------------------------
// Kernel 2: causal flash attention, all-fp16 mma16. 256 thr = 8 warps x 16
// query rows. K [key][kw], V^T [dv][sw]; K/V double-buffered cp.async.
// ---------------------------------------------------------------------------
__global__ __launch_bounds__(256, 2) void attn_mma()
{
    extern __shared__ uint32_t sm[];
    uint32_t (*Ks)[64][36] = (uint32_t(*)[64][36])sm;               // 2 bufs fp16 [key][kw]
    uint32_t (*Vs)[64][36] = (uint32_t(*)[64][36])(sm + 2*64*36);   // 2 bufs fp16 [dv][keyw]
    uint32_t (*Ps)[36]     = (uint32_t(*)[36])(sm + 4*64*36);       // 128x36 fp16 [row][keyw]
    uint32_t (*Qst)[36]    = (uint32_t(*)[36])Ps;                   // Q staging alias

    const int qt = 7 - blockIdx.x;
    const int bh = blockIdx.y;
    const int b = bh >> 4, h = bh & 15;
    const int tid = threadIdx.x, lane = tid & 31, warp = tid >> 5;
    const int g = lane >> 2, tig = lane & 3;

    const uint32_t* Qg = g_QH + (size_t)bh * S_ * (DK_/2) + (size_t)qt * 128 * (DK_/2);
    const uint32_t* Kg = g_KH + (size_t)bh * S_ * (DK_/2);
    const uint32_t* Vg = g_VH + (size_t)bh * DV_ * (S_/2);

    // stage Q tile (fp16 packed, pre-scaled) into Ps region
    #pragma unroll
    for (int t = 0; t < 4; t++) {
        int idx = tid + t * 256, r = idx >> 3, c = (idx & 7) * 4;
        cpa16(&Qst[r][c], &Qg[r * (DK_/2) + c]);
    }
    cpa_commit(); cpa_wait0();
    __syncthreads();

    uint32_t qf[4][4];
    {
        int rr = warp * 16 + g;
        #pragma unroll
        for (int ks = 0; ks < 4; ks++) {
            qf[ks][0] = Qst[rr][ks*8 + tig];
            qf[ks][1] = Qst[rr + 8][ks*8 + tig];
            qf[ks][2] = Qst[rr][ks*8 + tig + 4];
            qf[ks][3] = Qst[rr + 8][ks*8 + tig + 4];
        }
    }

    auto issueKV = [&](int j, int buf) {
        const uint32_t* Kt = Kg + (size_t)j * 64 * (DK_/2);
        #pragma unroll
        for (int t = 0; t < 2; t++) {            // K: 64 x 32 words
            int idx = tid + t * 256, r = idx >> 3, c = (idx & 7) * 4;
            cpa16(&Ks[buf][r][c], &Kt[r * (DK_/2) + c]);
        }
        #pragma unroll
        for (int t = 0; t < 2; t++) {            // V^T: 64 dv-rows x 32 key-words
            int idx = tid + t * 256, r = idx >> 3, c = (idx & 7) * 4;
            cpa16(&Vs[buf][r][c], &Vg[r * (S_/2) + j * 32 + c]);
        }
        cpa_commit();
    };

    float O[8][4];
    #pragma unroll
    for (int nt = 0; nt < 8; nt++)
        #pragma unroll
        for (int i = 0; i < 4; i++) O[nt][i] = 0.f;
    float mst[2] = {-1e30f, -1e30f};
    float lst[2] = {0.f, 0.f};

    const int base = qt * 128 + warp * 16;
    const int jmax = 2 * qt + 1;

    issueKV(0, 0);

    for (int j = 0; j <= jmax; j++) {
        const int buf = j & 1;
        __syncthreads();                 // prior compute done; Q hoist done (j=0)
        if (j < jmax) { issueKV(j + 1, buf ^ 1); cpa_wait1(); }
        else          { cpa_wait0(); }
        __syncthreads();

        if (j * 64 > base + 15) continue;

        // ---- S = Q K^T (fp16) ----
        float Sf[8][4];
        #pragma unroll
        for (int nt = 0; nt < 8; nt++)
            #pragma unroll
            for (int i = 0; i < 4; i++) Sf[nt][i] = 0.f;

        #pragma unroll
        for (int ks = 0; ks < 4; ks++) {
            #pragma unroll
            for (int nt = 0; nt < 8; nt++) {
                uint32_t bf[2];
                bf[0] = Ks[buf][nt*8 + g][ks*8 + tig];
                bf[1] = Ks[buf][nt*8 + g][ks*8 + tig + 4];
                mma16(Sf[nt], qf[ks], bf);
            }
        }

        if ((j + 1) * 64 > base) {
            int r0 = base + g - j * 64, r1 = r0 + 8;
            #pragma unroll
            for (int nt = 0; nt < 8; nt++) {
                int c0 = nt * 8 + 2 * tig, c1 = c0 + 1;
                if (c0 > r0) Sf[nt][0] = -1e30f;
                if (c1 > r0) Sf[nt][1] = -1e30f;
                if (c0 > r1) Sf[nt][2] = -1e30f;
                if (c1 > r1) Sf[nt][3] = -1e30f;
            }
        }

        #pragma unroll
        for (int hp = 0; hp < 2; hp++) {
            float mx = -1e30f;
            #pragma unroll
            for (int nt = 0; nt < 8; nt++)
                mx = fmaxf(mx, fmaxf(Sf[nt][2*hp], Sf[nt][2*hp+1]));
            mx = fmaxf(mx, __shfl_xor_sync(0xffffffffu, mx, 1));
            mx = fmaxf(mx, __shfl_xor_sync(0xffffffffu, mx, 2));
            const float mn = fmaxf(mst[hp], mx);
            const float fac = __expf(mst[hp] - mn);
            float ls = 0.f;
            const int rr = warp * 16 + g + 8 * hp;
            #pragma unroll
            for (int nt = 0; nt < 8; nt++) {
                float p0 = __expf(Sf[nt][2*hp]     - mn);
                float p1 = __expf(Sf[nt][2*hp + 1] - mn);
                ls += p0 + p1;
                Ps[rr][nt*4 + tig] = f2h2(p0, p1);   // fp16 pairs along key
                O[nt][2*hp]     *= fac;
                O[nt][2*hp + 1] *= fac;
            }
            ls += __shfl_xor_sync(0xffffffffu, ls, 1);
            ls += __shfl_xor_sync(0xffffffffu, ls, 2);
            lst[hp] = lst[hp] * fac + ls;
            mst[hp] = mn;
        }
        __syncwarp();   // each warp consumes only its own P rows

        // ---- O += P V (fp16) ----
        #pragma unroll
        for (int kt = 0; kt < 4; kt++) {
            uint32_t af[4];
            int rr = warp * 16 + g;
            af[0] = Ps[rr][kt*8 + tig];
            af[1] = Ps[rr + 8][kt*8 + tig];
            af[2] = Ps[rr][kt*8 + tig + 4];
            af[3] = Ps[rr + 8][kt*8 + tig + 4];
            #pragma unroll
            for (int nt = 0; nt < 8; nt++) {
                uint32_t bf[2];
                bf[0] = Vs[buf][nt*8 + g][kt*8 + tig];
                bf[1] = Vs[buf][nt*8 + g][kt*8 + tig + 4];
                mma16(O[nt], af, bf);
            }
        }
    }

    // epilogue: pack X as fp16x2 (out_proj operand)
    #pragma unroll
    for (int hp = 0; hp < 2; hp++) {
        const float rl = 1.f / lst[hp];
        const int row = base + g + 8 * hp;
        uint32_t* xp = g_XH + ((size_t)b * S_ + row) * (H_ * DV_ / 2) + h * (DV_/2);
        #pragma unroll
        for (int nt = 0; nt < 8; nt++)
            xp[nt * 4 + tig] = f2h2(O[nt][2*hp] * rl, O[nt][2*hp + 1] * rl);
    }
}

// ---------------------------------------------------------------------------
// Kernel 3: output projection (fp16 mma16). y[m,d] = sum_e X[m,e] * Wo[d,e].
// Block 128x128, 8 warps (4m x 2n), warp 32x64, K-chunk 64.
// ---------------------------------------------------------------------------
__global__ __launch_bounds__(256, 2) void out_proj_mma(float* __restrict__ y)
{
    extern __shared__ uint32_t smo[];
    uint32_t (*As)[128][36]  = (uint32_t(*)[128][36])smo;
    uint32_t (*Bsn)[128][36] = (uint32_t(*)[128][36])(smo + 2*128*36);

    const int m0 = blockIdx.x * 128;
    const int n0 = blockIdx.y * 128;

    const int tid = threadIdx.x, lane = tid & 31, warp = tid >> 5;
    const int wm = warp & 3, wn = warp >> 2;
    const int g = lane >> 2, tig = lane & 3;

    float acc[2][8][4];
    #pragma unroll
    for (int mt = 0; mt < 2; mt++)
        #pragma unroll
        for (int nt = 0; nt < 8; nt++)
            #pragma unroll
            for (int i = 0; i < 4; i++) acc[mt][nt][i] = 0.f;

    auto issue = [&](int k0w, int buf) {
        #pragma unroll
        for (int t = 0; t < 4; t++) {
            int idx = tid + t * 256, r = idx >> 3, c = (idx & 7) * 4;
            cpa16(&As[buf][r][c], &g_XH[(size_t)(m0 + r) * (DM_/2) + k0w + c]);
        }
        #pragma unroll
        for (int t = 0; t < 4; t++) {
            int idx = tid + t * 256, r = idx >> 3, c = (idx & 7) * 4;
            cpa16(&Bsn[buf][r][c], &g_WoH[(size_t)(n0 + r) * (DM_/2) + k0w + c]);
        }
        cpa_commit();
    };

    issue(0, 0);

    const int NCH = DM_ / 64;
    for (int it = 0; it < NCH; it++) {
        const int buf = it & 1;
        cpa_wait0();
        __syncthreads();
        if (it + 1 < NCH) issue((it + 1) * 32, buf ^ 1);

        #pragma unroll
        for (int ks = 0; ks < 4; ks++) {
            uint32_t af[2][4];
            #pragma unroll
            for (int mt = 0; mt < 2; mt++) {
                int rr = wm * 32 + mt * 16 + g;
                af[mt][0] = As[buf][rr][ks*8 + tig];
                af[mt][1] = As[buf][rr + 8][ks*8 + tig];
                af[mt][2] = As[buf][rr][ks*8 + tig + 4];
                af[mt][3] = As[buf][rr + 8][ks*8 + tig + 4];
            }
            #pragma unroll
            for (int nt = 0; nt < 8; nt++) {
                uint32_t bf[2];
                int n = wn * 64 + nt * 8 + g;
                bf[0] = Bsn[buf][n][ks*8 + tig];
                bf[1] = Bsn[buf][n][ks*8 + tig + 4];
                mma16(acc[0][nt], af[0], bf);
                mma16(acc[1][nt], af[1], bf);
            }
        }
    }

    #pragma unroll
    for (int mt = 0; mt < 2; mt++) {
        #pragma unroll
        for (int hf = 0; hf < 2; hf++) {
            int m = m0 + wm * 32 + mt * 16 + g + hf * 8;
            #pragma unroll
            for (int nt = 0; nt < 8; nt++) {
                int nn = n0 + wn * 64 + nt * 8 + 2 * tig;
                float2 val = hf ? make_float2(acc[mt][nt][2], acc[mt][nt][3])
                                : make_float2(acc[mt][nt][0], acc[mt][nt][1]);
                *(float2*)&y[(size_t)m * DM_ + nn] = val;
            }
        }
    }
}

// ---------------------------------------------------------------------------
extern "C" void kernel_launch(void* const* d_in, const int* in_sizes, int n_in,
                              void* d_out, int out_size)
{
    const float* q  = (const float*)d_in[0];
    const float* k  = (const float*)d_in[1];
    const float* v  = (const float*)d_in[2];
    const float* Wq = (const float*)d_in[3];
    const float* Wk = (const float*)d_in[4];
    const float* Wv = (const float*)d_in[5];
    const float* Wo = (const float*)d_in[6];
    float* y = (float*)d_out;

    const int gemm_smem = (2*128*36 + 2*128*36) * (int)sizeof(uint32_t);      // 73728
    const int attn_smem = (2*64*36 + 2*64*36 + 128*36) * (int)sizeof(uint32_t); // 55296
    cudaFuncSetAttribute(qkv_proj_mma, cudaFuncAttributeMaxDynamicSharedMemorySize, gemm_smem);
    cudaFuncSetAttribute(attn_mma, cudaFuncAttributeMaxDynamicSharedMemorySize, attn_smem);
    cudaFuncSetAttribute(out_proj_mma, cudaFuncAttributeMaxDynamicSharedMemorySize, gemm_smem);

    cvt_pack<<<dim3(NX_ / 2048, 4), 256>>>(q, k, v, Wo);
    cvt_wT<<<dim3(DM_ / 32, H_, 3), 256>>>(Wq, Wk, Wv);
    qkv_proj_mma<<<dim3(S_ * B_ / 128, H_ / 2, 3), 256, gemm_smem>>>();
    attn_mma<<<dim3(8, B_ * H_), 256, attn_smem>>>();
    out_proj_mma<<<dim3(S_ * B_ / 128, DM_ / 128), 256, gemm_smem>>>(y);
}